// round 8
// baseline (speedup 1.0000x reference)
#include <cuda_runtime.h>
#include <cuda_bf16.h>
#include <cstdint>
#include <math.h>

namespace {

typedef unsigned long long ull;
typedef __nv_bfloat16 bf16;

constexpr int  B_  = 128;
constexpr int  T_  = 256;
constexpr int  R_  = 130;
constexpr int  H_  = 1024;
constexpr int  H3_ = 3072;
constexpr int  Z2_ = 256;
constexpr int  C_  = 24;
constexpr int  ZC_ = 280;                 // Z2 + C
constexpr long BT_ = (long)B_ * T_;       // 32768
constexpr long BH_ = (long)B_ * H_;
constexpr long WN_ = (long)H3_ * H_;      // 3.1M weights per matrix
constexpr int  KPAD = 192;                // padded K for the R=130 GEMMs

constexpr int NB = 128;   // persistent grid size (must all be co-resident)

// smem geometry (k-chunk = 64 bf16, padded row = 144 bytes)
constexpr int KCH     = 64;
constexpr int ROWB    = 144;
constexpr int ABYTES  = 128 * ROWB;            // 18432
constexpr int BBYT_R  = 48  * ROWB;            // 6912  (recurrence: 48 W rows)
constexpr int STAGE_R = 2 * ABYTES + 2 * BBYT_R;   // 50688
constexpr int SMEM_R  = 2 * STAGE_R;               // 101376
constexpr int BBYT_G  = 64  * ROWB;            // 9216  (batched gemm: 64 W rows)
constexpr int STAGE_G = 2 * ABYTES + 2 * BBYT_G;   // 55296
constexpr int SMEM_G  = 2 * STAGE_G;               // 110592

// ------------------------- device scratch ----------------------------------
__device__ float g_hf[2][B_ * H_];
__device__ float g_hb[2][B_ * H_];
__device__ float g_h0[2][B_ * H_];
__device__ float g_h1[2][B_ * H_];
__device__ bf16 g_hfhi[2][B_ * H_], g_hflo[2][B_ * H_];
__device__ bf16 g_hbhi[2][B_ * H_], g_hblo[2][B_ * H_];
__device__ bf16 g_h0hi[2][B_ * H_], g_h0lo[2][B_ * H_];
__device__ bf16 g_h1hi[2][B_ * H_], g_h1lo[2][B_ * H_];
__device__ bf16 g_whhf_hi[WN_], g_whhf_lo[WN_];
__device__ bf16 g_whhb_hi[WN_], g_whhb_lo[WN_];
__device__ bf16 g_whhg_hi[WN_], g_whhg_lo[WN_];
__device__ bf16 g_wihg2_hi[WN_], g_wihg2_lo[WN_];
__device__ bf16 g_whhg2_hi[WN_], g_whhg2_lo[WN_];
// padded bf16 operands for the batched GEMMs
__device__ bf16 g_xc_hi[BT_ * KPAD],  g_xc_lo[BT_ * KPAD];
__device__ bf16 g_dc_hi[BT_ * KPAD],  g_dc_lo[BT_ * KPAD];
__device__ bf16 g_wihf_hi[H3_ * KPAD], g_wihf_lo[H3_ * KPAD];
__device__ bf16 g_wihb_hi[H3_ * KPAD], g_wihb_lo[H3_ * KPAD];
__device__ bf16 g_wihg_hi[H3_ * KPAD], g_wihg_lo[H3_ * KPAD];
__device__ bf16 g_wout_hi[192 * H_],  g_wout_lo[192 * H_];
__device__ bf16 g_h1a_hi[BT_ * H_],   g_h1a_lo[BT_ * H_];   // decoder h1 history
__device__ float g_gif[BT_ * H3_];        // encoder fwd input gates, row m=b*T+t
__device__ float g_gib[BT_ * H3_];        // encoder bwd input gates
__device__ float g_gid[BT_ * H3_];        // decoder dec_in input gates
__device__ float g_zi [B_ * H3_];         // z-part of decoder L1 gates (+b_ih_g)
__device__ float g_henc[B_ * 2 * H_];
__device__ float g_var [B_ * Z2_];
__device__ float g_zbuf[B_ * ZC_];
__device__ float g_decin[BT_ * R_];
__device__ float g_logits[BT_ * R_];
__device__ unsigned g_bar_count;
__device__ volatile unsigned g_bar_gen;

// --------------------------- small helpers ---------------------------------
__device__ __forceinline__ ull pack2(float x, float y) {
    ull r; asm("mov.b64 %0, {%1, %2};" : "=l"(r) : "f"(x), "f"(y)); return r;
}
__device__ __forceinline__ float2 unpack2(ull v) {
    float2 f; asm("mov.b64 {%0, %1}, %2;" : "=f"(f.x), "=f"(f.y) : "l"(v)); return f;
}
__device__ __forceinline__ void fma2(ull& d, ull a, ull b) {
    asm("fma.rn.f32x2 %0, %1, %2, %0;" : "+l"(d) : "l"(a), "l"(b));
}
__device__ __forceinline__ float sigmoidf_(float x) { return 1.f / (1.f + expf(-x)); }

__device__ __forceinline__ void ldsm4(uint32_t r[4], uint32_t addr) {
    asm volatile("ldmatrix.sync.aligned.m8n8.x4.shared.b16 {%0,%1,%2,%3}, [%4];"
                 : "=r"(r[0]), "=r"(r[1]), "=r"(r[2]), "=r"(r[3]) : "r"(addr));
}
__device__ __forceinline__ void ldsm2(uint32_t r[2], uint32_t addr) {
    asm volatile("ldmatrix.sync.aligned.m8n8.x2.shared.b16 {%0,%1}, [%2];"
                 : "=r"(r[0]), "=r"(r[1]) : "r"(addr));
}
__device__ __forceinline__ void mma16816(float d[4], const uint32_t a[4], const uint32_t b[2]) {
    asm volatile(
        "mma.sync.aligned.m16n8k16.row.col.f32.bf16.bf16.f32 "
        "{%0,%1,%2,%3}, {%4,%5,%6,%7}, {%8,%9}, {%0,%1,%2,%3};"
        : "+f"(d[0]), "+f"(d[1]), "+f"(d[2]), "+f"(d[3])
        : "r"(a[0]), "r"(a[1]), "r"(a[2]), "r"(a[3]), "r"(b[0]), "r"(b[1]));
}
__device__ __forceinline__ void cpa16(uint32_t dst, const void* src) {
    asm volatile("cp.async.cg.shared.global [%0], [%1], 16;" :: "r"(dst), "l"(src));
}
__device__ __forceinline__ void cp_commit() { asm volatile("cp.async.commit_group;"); }
template <int N> __device__ __forceinline__ void cp_wait() {
    asm volatile("cp.async.wait_group %0;" :: "n"(N));
}

// ------------------------ software grid barrier ----------------------------
__device__ __forceinline__ void grid_barrier() {
    __syncthreads();
    if (threadIdx.x == 0) {
        unsigned gen = g_bar_gen;
        __threadfence();
        if (atomicAdd(&g_bar_count, 1u) == (unsigned)(NB - 1)) {
            g_bar_count = 0;
            __threadfence();
            g_bar_gen = gen + 1;
        } else {
            while (g_bar_gen == gen) { }
        }
        __threadfence();
    }
    __syncthreads();
}

// --------------------- split-bf16 mma pass (recurrence) ---------------------
// C tile [128 x 48]: rows = batch, cols = 3 gates x 16 h-columns (j0..j0+15).
// acc[g][ct][4], K = 1024, A row stride H_.
__device__ __forceinline__ void mma_pass6(
    const bf16* __restrict__ Ah, const bf16* __restrict__ Al,
    const bf16* __restrict__ Wh, const bf16* __restrict__ Wl,
    int j0, uint32_t sm, float acc[3][2][4])
{
    const int tid  = threadIdx.x;
    const int lane = tid & 31;
    const int m0   = (tid >> 5) * 16;
    const int arow  = m0 + (lane & 15);
    const int ahalf = (lane >> 4) * 16;
    const int brow  = lane & 7;
    const int bhalf = ((lane >> 3) & 1) * 16;

    auto issue = [&](int c, int st) {
        uint32_t base = sm + st * STAGE_R;
        int k0 = c * KCH;
#pragma unroll
        for (int i = 0; i < 8; i++) {               // A: 128 rows hi+lo
            int u = tid + i * 256;
            int mat = u >= 1024; int r = mat ? u - 1024 : u;
            int row = r >> 3, seg = r & 7;
            cpa16(base + (mat ? ABYTES : 0) + row * ROWB + seg * 16,
                  (mat ? Al : Ah) + (long)row * H_ + k0 + seg * 8);
        }
#pragma unroll
        for (int i = 0; i < 3; i++) {               // W: 48 rows hi+lo
            int u = tid + i * 256;
            int mat = u >= 384; int r = mat ? u - 384 : u;
            int row = r >> 3, seg = r & 7;
            int g = row >> 4, rr = row & 15;
            long woff = (long)(g * H_ + j0 + rr) * H_ + k0 + seg * 8;
            cpa16(base + 2 * ABYTES + (mat ? BBYT_R : 0) + row * ROWB + seg * 16,
                  (mat ? Wl : Wh) + woff);
        }
    };

    issue(0, 0); cp_commit();
#pragma unroll 1
    for (int c = 0; c < 16; c++) {
        if (c < 15) { issue(c + 1, (c + 1) & 1); cp_commit(); cp_wait<1>(); }
        else        { cp_wait<0>(); }
        __syncthreads();
        uint32_t base = sm + (c & 1) * STAGE_R;
#pragma unroll
        for (int s = 0; s < 4; s++) {
            uint32_t aoff = base + arow * ROWB + ahalf + s * 32;
            uint32_t a_hi[4], a_lo[4];
            ldsm4(a_hi, aoff);
            ldsm4(a_lo, aoff + ABYTES);
#pragma unroll
            for (int g = 0; g < 3; g++)
#pragma unroll
            for (int ct = 0; ct < 2; ct++) {
                uint32_t boff = base + 2 * ABYTES + (g * 16 + ct * 8 + brow) * ROWB + bhalf + s * 32;
                uint32_t b_hi[2], b_lo[2];
                ldsm2(b_hi, boff);
                ldsm2(b_lo, boff + BBYT_R);
                mma16816(acc[g][ct], a_hi, b_hi);
                mma16816(acc[g][ct], a_hi, b_lo);
                mma16816(acc[g][ct], a_lo, b_hi);
            }
        }
        __syncthreads();
    }
}

// Fused GRU epilogue on mma fragments (single input-gate source).
__device__ __forceinline__ void gru_epi2(
    const float acc[3][2][4], const float* __restrict__ gi, int tstep,
    const float bh2[2][6], const float* __restrict__ hprev,
    float* __restrict__ hn, bf16* __restrict__ hhi, bf16* __restrict__ hlo,
    int m0, int lane, int j0)
{
#pragma unroll
    for (int ct = 0; ct < 2; ct++) {
        int jj = j0 + ct * 8 + (lane & 3) * 2;
#pragma unroll
        for (int half = 0; half < 2; half++) {
            int m = m0 + (lane >> 2) + half * 8;
            long gb = ((long)m * T_ + tstep) * H3_ + jj;
            float2 gr = *(const float2*)(gi + gb);
            float2 gz = *(const float2*)(gi + gb + H_);
            float2 gn = *(const float2*)(gi + gb + 2 * H_);
            float2 hp = *(const float2*)(hprev + (long)m * H_ + jj);
            float r0 = sigmoidf_(gr.x + acc[0][ct][half * 2]     + bh2[ct][0]);
            float r1 = sigmoidf_(gr.y + acc[0][ct][half * 2 + 1] + bh2[ct][1]);
            float u0 = sigmoidf_(gz.x + acc[1][ct][half * 2]     + bh2[ct][2]);
            float u1 = sigmoidf_(gz.y + acc[1][ct][half * 2 + 1] + bh2[ct][3]);
            float n0 = tanhf(gn.x + r0 * (acc[2][ct][half * 2]     + bh2[ct][4]));
            float n1 = tanhf(gn.y + r1 * (acc[2][ct][half * 2 + 1] + bh2[ct][5]));
            float v0 = (1.f - u0) * n0 + u0 * hp.x;
            float v1 = (1.f - u1) * n1 + u1 * hp.y;
            *(float2*)(hn + (long)m * H_ + jj) = make_float2(v0, v1);
            bf16 h0 = __float2bfloat16(v0);
            bf16 h1 = __float2bfloat16(v1);
            *(__nv_bfloat162*)(hhi + (long)m * H_ + jj) = __nv_bfloat162(h0, h1);
            *(__nv_bfloat162*)(hlo + (long)m * H_ + jj) = __nv_bfloat162(
                __float2bfloat16(v0 - __bfloat162float(h0)),
                __float2bfloat16(v1 - __bfloat162float(h1)));
        }
    }
}

// -------------------- persistent encoder (bidirectional GRU) ---------------
// CTAs 0..63: forward direction; 64..127: backward. 16 h-cols per CTA.
__global__ void __launch_bounds__(256, 1)
encoder_kernel(const float* __restrict__ bh_f, const float* __restrict__ bh_b) {
    extern __shared__ char smem[];
    uint32_t sm = (uint32_t)__cvta_generic_to_shared(smem);
    const int tid = threadIdx.x, lane = tid & 31;
    const int m0 = (tid >> 5) * 16;
    const int dir = blockIdx.x >> 6;
    const int j0 = (blockIdx.x & 63) * 16;

    const bf16* Wh = dir ? g_whhb_hi : g_whhf_hi;
    const bf16* Wl = dir ? g_whhb_lo : g_whhf_lo;
    const float* gi = dir ? g_gib : g_gif;
    const float* bh = dir ? bh_b : bh_f;

    float bh2[2][6];
#pragma unroll
    for (int ct = 0; ct < 2; ct++) {
        int jj = j0 + ct * 8 + (lane & 3) * 2;
#pragma unroll
        for (int g = 0; g < 3; g++) {
            bh2[ct][g * 2]     = bh[g * H_ + jj];
            bh2[ct][g * 2 + 1] = bh[g * H_ + jj + 1];
        }
    }

#pragma unroll 1
    for (int t = 0; t < T_; t++) {
        const int cur = t & 1, nxt = cur ^ 1;
        const bf16* Ah = dir ? g_hbhi[cur] : g_hfhi[cur];
        const bf16* Al = dir ? g_hblo[cur] : g_hflo[cur];
        const float* hc = dir ? g_hb[cur] : g_hf[cur];
        float*       hn = dir ? g_hb[nxt] : g_hf[nxt];
        bf16* hhi = dir ? g_hbhi[nxt] : g_hfhi[nxt];
        bf16* hlo = dir ? g_hblo[nxt] : g_hflo[nxt];
        float acc[3][2][4] = {};
        mma_pass6(Ah, Al, Wh, Wl, j0, sm, acc);
        gru_epi2(acc, gi, dir ? (T_ - 1 - t) : t, bh2, hc, hn, hhi, hlo, m0, lane, j0);
        grid_barrier();
    }
}

// -------------------- persistent decoder (2-layer GRU) ---------------------
// CTAs 0..63 active (16 h-cols each); 64..127 only participate in barriers.
__global__ void __launch_bounds__(256, 1)
decoder_kernel(const float* __restrict__ b_hh_g,
               const float* __restrict__ b_ih_g2, const float* __restrict__ b_hh_g2) {
    extern __shared__ char smem[];
    uint32_t sm = (uint32_t)__cvta_generic_to_shared(smem);
    const int tid = threadIdx.x, lane = tid & 31;
    const int m0 = (tid >> 5) * 16;
    const bool active = blockIdx.x < 64;
    const int j0 = (blockIdx.x & 63) * 16;

    float bg2[2][6], bi2[2][6], bh2[2][6];
#pragma unroll
    for (int ct = 0; ct < 2; ct++) {
        int jj = j0 + ct * 8 + (lane & 3) * 2;
#pragma unroll
        for (int g = 0; g < 3; g++) {
            bg2[ct][g * 2] = b_hh_g[g * H_ + jj];   bg2[ct][g * 2 + 1] = b_hh_g[g * H_ + jj + 1];
            bi2[ct][g * 2] = b_ih_g2[g * H_ + jj];  bi2[ct][g * 2 + 1] = b_ih_g2[g * H_ + jj + 1];
            bh2[ct][g * 2] = b_hh_g2[g * H_ + jj];  bh2[ct][g * 2 + 1] = b_hh_g2[g * H_ + jj + 1];
        }
    }

#pragma unroll 1
    for (int t = 0; t < T_; t++) {
        const int cur = t & 1, nxt = cur ^ 1;
        // ------- phase A: layer-1 GRU -------
        if (active) {
            float acc[3][2][4] = {};
            mma_pass6(g_h0hi[cur], g_h0lo[cur], g_whhg_hi, g_whhg_lo, j0, sm, acc);
#pragma unroll
            for (int ct = 0; ct < 2; ct++) {
                int jj = j0 + ct * 8 + (lane & 3) * 2;
#pragma unroll
                for (int half = 0; half < 2; half++) {
                    int m = m0 + (lane >> 2) + half * 8;
                    long gb = ((long)m * T_ + t) * H3_ + jj;
                    long zb = (long)m * H3_ + jj;
                    float2 gr = *(const float2*)(g_gid + gb);
                    float2 gz = *(const float2*)(g_gid + gb + H_);
                    float2 gn = *(const float2*)(g_gid + gb + 2 * H_);
                    float2 zr = *(const float2*)(g_zi + zb);
                    float2 zz = *(const float2*)(g_zi + zb + H_);
                    float2 zn = *(const float2*)(g_zi + zb + 2 * H_);
                    float2 hp = *(const float2*)(g_h0[cur] + (long)m * H_ + jj);
                    float r0 = sigmoidf_(gr.x + zr.x + acc[0][ct][half * 2]     + bg2[ct][0]);
                    float r1 = sigmoidf_(gr.y + zr.y + acc[0][ct][half * 2 + 1] + bg2[ct][1]);
                    float u0 = sigmoidf_(gz.x + zz.x + acc[1][ct][half * 2]     + bg2[ct][2]);
                    float u1 = sigmoidf_(gz.y + zz.y + acc[1][ct][half * 2 + 1] + bg2[ct][3]);
                    float n0 = tanhf(gn.x + zn.x + r0 * (acc[2][ct][half * 2]     + bg2[ct][4]));
                    float n1 = tanhf(gn.y + zn.y + r1 * (acc[2][ct][half * 2 + 1] + bg2[ct][5]));
                    float v0 = (1.f - u0) * n0 + u0 * hp.x;
                    float v1 = (1.f - u1) * n1 + u1 * hp.y;
                    *(float2*)(g_h0[nxt] + (long)m * H_ + jj) = make_float2(v0, v1);
                    bf16 h0b = __float2bfloat16(v0);
                    bf16 h1b = __float2bfloat16(v1);
                    *(__nv_bfloat162*)(g_h0hi[nxt] + (long)m * H_ + jj) = __nv_bfloat162(h0b, h1b);
                    *(__nv_bfloat162*)(g_h0lo[nxt] + (long)m * H_ + jj) = __nv_bfloat162(
                        __float2bfloat16(v0 - __bfloat162float(h0b)),
                        __float2bfloat16(v1 - __bfloat162float(h1b)));
                }
            }
        }
        grid_barrier();
        // ------- phase B: layer-2 GRU -------
        if (active) {
            const bf16* h1p_hi = (t == 0) ? g_h0hi[nxt] : g_h1hi[cur];
            const bf16* h1p_lo = (t == 0) ? g_h0lo[nxt] : g_h1lo[cur];
            const float* h1p_f = (t == 0) ? g_h0[nxt]   : g_h1[cur];
            float accI[3][2][4] = {};
            float accH[3][2][4] = {};
            mma_pass6(g_h0hi[nxt], g_h0lo[nxt], g_wihg2_hi, g_wihg2_lo, j0, sm, accI);
            mma_pass6(h1p_hi, h1p_lo, g_whhg2_hi, g_whhg2_lo, j0, sm, accH);
#pragma unroll
            for (int ct = 0; ct < 2; ct++) {
                int jj = j0 + ct * 8 + (lane & 3) * 2;
#pragma unroll
                for (int half = 0; half < 2; half++) {
                    int m = m0 + (lane >> 2) + half * 8;
                    float2 hp = *(const float2*)(h1p_f + (long)m * H_ + jj);
                    float r0 = sigmoidf_((accI[0][ct][half * 2]     + bi2[ct][0]) + (accH[0][ct][half * 2]     + bh2[ct][0]));
                    float r1 = sigmoidf_((accI[0][ct][half * 2 + 1] + bi2[ct][1]) + (accH[0][ct][half * 2 + 1] + bh2[ct][1]));
                    float u0 = sigmoidf_((accI[1][ct][half * 2]     + bi2[ct][2]) + (accH[1][ct][half * 2]     + bh2[ct][2]));
                    float u1 = sigmoidf_((accI[1][ct][half * 2 + 1] + bi2[ct][3]) + (accH[1][ct][half * 2 + 1] + bh2[ct][3]));
                    float n0 = tanhf((accI[2][ct][half * 2]     + bi2[ct][4]) + r0 * (accH[2][ct][half * 2]     + bh2[ct][4]));
                    float n1 = tanhf((accI[2][ct][half * 2 + 1] + bi2[ct][5]) + r1 * (accH[2][ct][half * 2 + 1] + bh2[ct][5]));
                    float v0 = (1.f - u0) * n0 + u0 * hp.x;
                    float v1 = (1.f - u1) * n1 + u1 * hp.y;
                    *(float2*)(g_h1[nxt] + (long)m * H_ + jj) = make_float2(v0, v1);
                    bf16 h0b = __float2bfloat16(v0);
                    bf16 h1b = __float2bfloat16(v1);
                    bf16 l0 = __float2bfloat16(v0 - __bfloat162float(h0b));
                    bf16 l1 = __float2bfloat16(v1 - __bfloat162float(h1b));
                    *(__nv_bfloat162*)(g_h1hi[nxt] + (long)m * H_ + jj) = __nv_bfloat162(h0b, h1b);
                    *(__nv_bfloat162*)(g_h1lo[nxt] + (long)m * H_ + jj) = __nv_bfloat162(l0, l1);
                    long ho = ((long)m * T_ + t) * H_ + jj;
                    *(__nv_bfloat162*)(g_h1a_hi + ho) = __nv_bfloat162(h0b, h1b);
                    *(__nv_bfloat162*)(g_h1a_lo + ho) = __nv_bfloat162(l0, l1);
                }
            }
        }
        grid_barrier();
    }
}

// ------------------- split-bf16 batched GEMM (tensor cores) -----------------
// C[M,N] = A[M,K] @ W[N,K]^T + bias. A/W as bf16 hi/lo, fp32 out.
// Tile: 128(M) x 64(N), K consumed in kchunks chunks of 64.
struct BfArgs {
    const bf16 *Ah, *Al, *Wh, *Wl;
    const float* bias;
    float* C;
    long lda, ldb, ldc;
    int  N, kchunks;
};

__global__ void __launch_bounds__(256, 2) gemm_bf16_kernel(BfArgs a) {
    extern __shared__ char smem[];
    uint32_t sm = (uint32_t)__cvta_generic_to_shared(smem);
    const long bm = (long)blockIdx.y * 128;
    const int  bn = blockIdx.x * 64;
    const int tid = threadIdx.x, lane = tid & 31;
    const int m0 = (tid >> 5) * 16;
    const int arow  = m0 + (lane & 15);
    const int ahalf = (lane >> 4) * 16;
    const int brow  = lane & 7;
    const int bhalf = ((lane >> 3) & 1) * 16;

    float acc[8][4];
#pragma unroll
    for (int nt = 0; nt < 8; nt++)
#pragma unroll
        for (int q = 0; q < 4; q++) acc[nt][q] = 0.f;

    auto issue = [&](int c, int st) {
        uint32_t base = sm + st * STAGE_G;
        long k0 = (long)c * KCH;
#pragma unroll
        for (int i = 0; i < 8; i++) {
            int u = tid + i * 256;
            int mat = u >= 1024; int r = mat ? u - 1024 : u;
            int row = r >> 3, seg = r & 7;
            cpa16(base + (mat ? ABYTES : 0) + row * ROWB + seg * 16,
                  (mat ? a.Al : a.Ah) + (bm + row) * a.lda + k0 + seg * 8);
        }
#pragma unroll
        for (int i = 0; i < 4; i++) {
            int u = tid + i * 256;
            int mat = u >= 512; int r = mat ? u - 512 : u;
            int row = r >> 3, seg = r & 7;
            cpa16(base + 2 * ABYTES + (mat ? BBYT_G : 0) + row * ROWB + seg * 16,
                  (mat ? a.Wl : a.Wh) + (long)(bn + row) * a.ldb + k0 + seg * 8);
        }
    };

    issue(0, 0); cp_commit();
#pragma unroll 1
    for (int c = 0; c < a.kchunks; c++) {
        if (c < a.kchunks - 1) { issue(c + 1, (c + 1) & 1); cp_commit(); cp_wait<1>(); }
        else                   { cp_wait<0>(); }
        __syncthreads();
        uint32_t base = sm + (c & 1) * STAGE_G;
#pragma unroll
        for (int s = 0; s < 4; s++) {
            uint32_t aoff = base + arow * ROWB + ahalf + s * 32;
            uint32_t a_hi[4], a_lo[4];
            ldsm4(a_hi, aoff);
            ldsm4(a_lo, aoff + ABYTES);
#pragma unroll
            for (int nt = 0; nt < 8; nt++) {
                uint32_t boff = base + 2 * ABYTES + (nt * 8 + brow) * ROWB + bhalf + s * 32;
                uint32_t b_hi[2], b_lo[2];
                ldsm2(b_hi, boff);
                ldsm2(b_lo, boff + BBYT_G);
                mma16816(acc[nt], a_hi, b_hi);
                mma16816(acc[nt], a_hi, b_lo);
                mma16816(acc[nt], a_lo, b_hi);
            }
        }
        __syncthreads();
    }

#pragma unroll
    for (int nt = 0; nt < 8; nt++) {
        int gn = bn + nt * 8 + (lane & 3) * 2;
        float b0 = 0.f, b1 = 0.f;
        if (a.bias) {
            if (gn < a.N)     b0 = a.bias[gn];
            if (gn + 1 < a.N) b1 = a.bias[gn + 1];
        }
#pragma unroll
        for (int half = 0; half < 2; half++) {
            long m = bm + m0 + (lane >> 2) + half * 8;
            if (gn < a.N)     a.C[m * a.ldc + gn]     = acc[nt][half * 2]     + b0;
            if (gn + 1 < a.N) a.C[m * a.ldc + gn + 1] = acc[nt][half * 2 + 1] + b1;
        }
    }
}

// ------------------------------- fp32 GEMM ----------------------------------
// (small VAE-head GEMMs only)
struct GArgs {
    const float* A;  long lda;
    const float* W;  long ldw;
    const float* bias;
    float*       C;  long ldc;
    int M, N, K;
};

constexpr int GBM = 128, GBN = 128, GBK = 16;

__global__ void __launch_bounds__(256, 2) gemm_nt_kernel(GArgs g0, GArgs g1) {
    GArgs g = (blockIdx.z == 0) ? g0 : g1;
    const int bm = blockIdx.y * GBM;
    const int bn = blockIdx.x * GBN;
    if (bm >= g.M || bn >= g.N) return;

    __shared__ float As[GBK][GBM + 4];
    __shared__ ull   Bs[GBK][GBN + 1];

    const int tid = threadIdx.x;
    const int tx  = tid & 15;
    const int ty  = tid >> 4;
    const int r0  = ty * 8;

    ull acc[4][8];
#pragma unroll
    for (int p = 0; p < 4; p++)
#pragma unroll
        for (int c = 0; c < 8; c++) acc[p][c] = 0ull;

    for (int k0 = 0; k0 < g.K; k0 += GBK) {
#pragma unroll
        for (int i = 0; i < 8; i++) {
            int idx = tid + i * 256;
            int m = idx >> 4, kk = idx & 15;
            int gm = bm + m, gk = k0 + kk;
            float v = 0.f;
            if (gm < g.M && gk < g.K) v = g.A[(long)gm * g.lda + gk];
            As[kk][m] = v;
        }
#pragma unroll
        for (int i = 0; i < 8; i++) {
            int idx = tid + i * 256;
            int n = idx >> 4, kk = idx & 15;
            int gn = bn + n, gk = k0 + kk;
            float v = 0.f;
            if (gn < g.N && gk < g.K) v = g.W[(long)gn * g.ldw + gk];
            Bs[kk][(n & 7) * 16 + (n >> 3)] = pack2(v, v);
        }
        __syncthreads();
#pragma unroll
        for (int kk = 0; kk < GBK; kk++) {
            ull a[4], b[8];
#pragma unroll
            for (int p = 0; p < 4; p++) a[p] = *(const ull*)&As[kk][r0 + 2 * p];
#pragma unroll
            for (int c = 0; c < 8; c++) b[c] = Bs[kk][c * 16 + tx];
#pragma unroll
            for (int p = 0; p < 4; p++)
#pragma unroll
                for (int c = 0; c < 8; c++) fma2(acc[p][c], a[p], b[c]);
        }
        __syncthreads();
    }

#pragma unroll
    for (int p = 0; p < 4; p++) {
        int gm = bm + r0 + 2 * p;
#pragma unroll
        for (int c = 0; c < 8; c++) {
            int gn = bn + tx * 8 + c;
            if (gn >= g.N) continue;
            float2 v = unpack2(acc[p][c]);
            float bias = g.bias ? g.bias[gn] : 0.f;
            if (gm < g.M)     g.C[(long)gm * g.ldc + gn]       = v.x + bias;
            if (gm + 1 < g.M) g.C[(long)(gm + 1) * g.ldc + gn] = v.y + bias;
        }
    }
}

// --------------------------- elementwise kernels ---------------------------
__global__ void init_kernel(const float* __restrict__ x) {
    long stride = (long)gridDim.x * blockDim.x;
    long i0 = (long)blockIdx.x * blockDim.x + threadIdx.x;
    if (i0 == 0) { g_bar_count = 0; g_bar_gen = 0; }
    for (long i = i0; i < BH_; i += stride) {
        g_hf[0][i] = 0.f; g_hb[0][i] = 0.f;
        g_hfhi[0][i] = bf16(0.f); g_hflo[0][i] = bf16(0.f);
        g_hbhi[0][i] = bf16(0.f); g_hblo[0][i] = bf16(0.f);
    }
    for (long i = i0; i < BT_ * R_; i += stride) {
        int  r = (int)(i % R_);
        long m = i / R_;
        int  t = (int)(m % T_);
        g_decin[i] = (t == 0) ? ((r == R_ - 1) ? 1.f : 0.f) : x[i - R_];
    }
}

__global__ void convert_w_kernel(const float* __restrict__ src,
                                 bf16* __restrict__ hi, bf16* __restrict__ lo, long n) {
    long stride = (long)gridDim.x * blockDim.x;
    for (long i = (long)blockIdx.x * blockDim.x + threadIdx.x; i < n; i += stride) {
        float w = src[i];
        bf16 h = __float2bfloat16(w);
        hi[i] = h;
        lo[i] = __float2bfloat16(w - __bfloat162float(h));
    }
}

// convert with column/row padding: dst [rows x dstld], src [srcrows x srcld]
__global__ void convert_pad_kernel(const float* __restrict__ src, long srcld,
                                   long srcrows, int cols, long dstld, long rows,
                                   bf16* __restrict__ hi, bf16* __restrict__ lo) {
    long stride = (long)gridDim.x * blockDim.x;
    long total = rows * dstld;
    for (long i = (long)blockIdx.x * blockDim.x + threadIdx.x; i < total; i += stride) {
        long r = i / dstld;
        long c = i - r * dstld;
        float v = (r < srcrows && c < cols) ? src[r * srcld + c] : 0.f;
        bf16 h = __float2bfloat16(v);
        hi[i] = h;
        lo[i] = __float2bfloat16(v - __bfloat162float(h));
    }
}

__global__ void henc_kernel() {
    int i = blockIdx.x * blockDim.x + threadIdx.x;
    if (i >= B_ * H_) return;
    int b = i / H_, jj = i % H_;
    g_henc[(long)b * 2 * H_ + jj]      = g_hf[0][i];
    g_henc[(long)b * 2 * H_ + H_ + jj] = g_hb[0][i];
}

__global__ void zstd_kernel(const float* __restrict__ eps,
                            const float* __restrict__ chroma,
                            const float* __restrict__ mu_out,
                            float* __restrict__ std_out,
                            float* __restrict__ z_out) {
    int b = blockIdx.x;
    int jj = threadIdx.x;
    if (jj < Z2_) {
        float mu = mu_out[(long)b * Z2_ + jj];
        float sd = expf(g_var[(long)b * Z2_ + jj]);
        float z  = mu + sd * eps[(long)b * Z2_ + jj];
        std_out[(long)b * Z2_ + jj] = sd;
        z_out[(long)b * ZC_ + jj]   = z;
        g_zbuf[(long)b * ZC_ + jj]  = z;
    } else if (jj < ZC_) {
        float cv = chroma[(long)b * C_ + (jj - Z2_)];
        z_out[(long)b * ZC_ + jj]  = cv;
        g_zbuf[(long)b * ZC_ + jj] = cv;
    }
}

__global__ void logsoftmax_kernel(const float* __restrict__ logits,
                                  float* __restrict__ out) {
    long warp = ((long)blockIdx.x * blockDim.x + threadIdx.x) >> 5;
    int  lane = threadIdx.x & 31;
    if (warp >= BT_) return;
    const float* row = logits + warp * R_;
    float mx = -1e30f;
    for (int jj = lane; jj < R_; jj += 32) mx = fmaxf(mx, row[jj]);
#pragma unroll
    for (int o = 16; o; o >>= 1) mx = fmaxf(mx, __shfl_xor_sync(0xffffffff, mx, o));
    float s = 0.f;
    for (int jj = lane; jj < R_; jj += 32) s += expf(row[jj] - mx);
#pragma unroll
    for (int o = 16; o; o >>= 1) s += __shfl_xor_sync(0xffffffff, s, o);
    float lse = mx + logf(s);
    float* orow = out + warp * R_;
    for (int jj = lane; jj < R_; jj += 32) orow[jj] = row[jj] - lse;
}

// ------------------------------ host helpers -------------------------------
static void launch_gemm2(const GArgs& a, const GArgs& b) {
    int M = a.M > b.M ? a.M : b.M;
    int N = a.N > b.N ? a.N : b.N;
    dim3 grid((N + GBN - 1) / GBN, (M + GBM - 1) / GBM, 2);
    gemm_nt_kernel<<<grid, 256>>>(a, b);
}
static void launch_bf_gemm(const BfArgs& a) {
    dim3 grid((a.N + 63) / 64, (32768) / 128, 1);
    gemm_bf16_kernel<<<grid, 256, SMEM_G>>>(a);
}
template <typename Tp>
static float* sym_addr(Tp& sym) {
    void* p = nullptr;
    cudaGetSymbolAddress(&p, sym);
    return (float*)p;
}
template <typename Tp>
static bf16* sym_addr_bf(Tp& sym) {
    void* p = nullptr;
    cudaGetSymbolAddress(&p, sym);
    return (bf16*)p;
}

} // anonymous namespace

extern "C" void kernel_launch(void* const* d_in, const int* in_sizes, int n_in,
                              void* d_out, int out_size) {
    (void)in_sizes; (void)n_in; (void)out_size;
    const float* x        = (const float*)d_in[0];
    const float* chroma   = (const float*)d_in[1];
    const float* eps      = (const float*)d_in[2];
    const float* w_ih_f   = (const float*)d_in[3];
    const float* w_hh_f   = (const float*)d_in[4];
    const float* b_ih_f   = (const float*)d_in[5];
    const float* b_hh_f   = (const float*)d_in[6];
    const float* w_ih_b   = (const float*)d_in[7];
    const float* w_hh_b   = (const float*)d_in[8];
    const float* b_ih_b   = (const float*)d_in[9];
    const float* b_hh_b   = (const float*)d_in[10];
    const float* w_mu     = (const float*)d_in[11];
    const float* b_mu     = (const float*)d_in[12];
    const float* w_var    = (const float*)d_in[13];
    const float* b_var    = (const float*)d_in[14];
    const float* w_init   = (const float*)d_in[15];
    const float* b_init   = (const float*)d_in[16];
    const float* w_ih_g   = (const float*)d_in[17];
    const float* w_hh_g   = (const float*)d_in[18];
    const float* b_ih_g   = (const float*)d_in[19];
    const float* b_hh_g   = (const float*)d_in[20];
    const float* w_ih_g2  = (const float*)d_in[21];
    const float* w_hh_g2  = (const float*)d_in[22];
    const float* b_ih_g2  = (const float*)d_in[23];
    const float* b_hh_g2  = (const float*)d_in[24];
    const float* w_out    = (const float*)d_in[25];
    const float* b_out    = (const float*)d_in[26];

    float* out = (float*)d_out;
    const long MU_OFF  = BT_ * R_;
    const long STD_OFF = MU_OFF + (long)B_ * Z2_;
    const long Z_OFF   = STD_OFF + (long)B_ * Z2_;

    float* p_gif   = sym_addr(g_gif);
    float* p_gib   = sym_addr(g_gib);
    float* p_gid   = sym_addr(g_gid);
    float* p_zi    = sym_addr(g_zi);
    float* p_h0    = sym_addr(g_h0);
    float* p_henc  = sym_addr(g_henc);
    float* p_var   = sym_addr(g_var);
    float* p_zbuf  = sym_addr(g_zbuf);
    float* p_decin = sym_addr(g_decin);
    float* p_logit = sym_addr(g_logits);

    cudaFuncSetAttribute(encoder_kernel,  cudaFuncAttributeMaxDynamicSharedMemorySize, SMEM_R);
    cudaFuncSetAttribute(decoder_kernel,  cudaFuncAttributeMaxDynamicSharedMemorySize, SMEM_R);
    cudaFuncSetAttribute(gemm_bf16_kernel, cudaFuncAttributeMaxDynamicSharedMemorySize, SMEM_G);

    // 1. prologue: zero h (fp32 + bf16), reset barrier, build dec_in fp32
    init_kernel<<<512, 256>>>(x);

    // 1b. recurrent weights -> split-bf16
    convert_w_kernel<<<512, 256>>>(w_hh_f,  sym_addr_bf(g_whhf_hi),  sym_addr_bf(g_whhf_lo),  WN_);
    convert_w_kernel<<<512, 256>>>(w_hh_b,  sym_addr_bf(g_whhb_hi),  sym_addr_bf(g_whhb_lo),  WN_);
    convert_w_kernel<<<512, 256>>>(w_hh_g,  sym_addr_bf(g_whhg_hi),  sym_addr_bf(g_whhg_lo),  WN_);
    convert_w_kernel<<<512, 256>>>(w_ih_g2, sym_addr_bf(g_wihg2_hi), sym_addr_bf(g_wihg2_lo), WN_);
    convert_w_kernel<<<512, 256>>>(w_hh_g2, sym_addr_bf(g_whhg2_hi), sym_addr_bf(g_whhg2_lo), WN_);

    // 1c. batched-GEMM operands -> split-bf16 with K padding
    convert_pad_kernel<<<1024, 256>>>(x,       R_,  BT_,  R_,  KPAD, BT_,
                                      sym_addr_bf(g_xc_hi), sym_addr_bf(g_xc_lo));
    convert_pad_kernel<<<1024, 256>>>(p_decin, R_,  BT_,  R_,  KPAD, BT_,
                                      sym_addr_bf(g_dc_hi), sym_addr_bf(g_dc_lo));
    convert_pad_kernel<<<512, 256>>>(w_ih_f,  R_,  H3_,  R_,  KPAD, H3_,
                                     sym_addr_bf(g_wihf_hi), sym_addr_bf(g_wihf_lo));
    convert_pad_kernel<<<512, 256>>>(w_ih_b,  R_,  H3_,  R_,  KPAD, H3_,
                                     sym_addr_bf(g_wihb_hi), sym_addr_bf(g_wihb_lo));
    convert_pad_kernel<<<512, 256>>>(w_ih_g,  410, H3_,  R_,  KPAD, H3_,
                                     sym_addr_bf(g_wihg_hi), sym_addr_bf(g_wihg_lo));
    convert_pad_kernel<<<256, 256>>>(w_out,   H_,  R_,   H_,  H_,   192,
                                     sym_addr_bf(g_wout_hi), sym_addr_bf(g_wout_lo));

    // 2. encoder input gates (both directions), tensor cores
    launch_bf_gemm({sym_addr_bf(g_xc_hi), sym_addr_bf(g_xc_lo),
                    sym_addr_bf(g_wihf_hi), sym_addr_bf(g_wihf_lo),
                    b_ih_f, p_gif, KPAD, KPAD, H3_, H3_, KPAD / KCH});
    launch_bf_gemm({sym_addr_bf(g_xc_hi), sym_addr_bf(g_xc_lo),
                    sym_addr_bf(g_wihb_hi), sym_addr_bf(g_wihb_lo),
                    b_ih_b, p_gib, KPAD, KPAD, H3_, H3_, KPAD / KCH});

    // 3. decoder dec_in input gates (first 130 cols of w_ih_g), tensor cores
    launch_bf_gemm({sym_addr_bf(g_dc_hi), sym_addr_bf(g_dc_lo),
                    sym_addr_bf(g_wihg_hi), sym_addr_bf(g_wihg_lo),
                    nullptr, p_gid, KPAD, KPAD, H3_, H3_, KPAD / KCH});

    // 4. persistent bidirectional encoder recurrence (fwd/bwd across CTA halves)
    encoder_kernel<<<NB, 256, SMEM_R>>>(b_hh_f, b_hh_b);

    // 5. concat final hiddens
    henc_kernel<<<(B_ * H_ + 255) / 256, 256>>>();

    // 6. VAE head (small fp32 GEMMs)
    GArgs gmu {p_henc, 2 * H_, w_mu,  2 * H_, b_mu,  out + MU_OFF, Z2_, B_, Z2_, 2 * H_};
    GArgs gvar{p_henc, 2 * H_, w_var, 2 * H_, b_var, p_var,        Z2_, B_, Z2_, 2 * H_};
    launch_gemm2(gmu, gvar);

    // 7. reparameterize + concat chroma
    zstd_kernel<<<B_, 288>>>(eps, chroma, out + MU_OFF, out + STD_OFF, out + Z_OFF);

    // 8. hx0 = z @ w_init^T + b_init ; zi = z @ w_ih_g[:,130:]^T + b_ih_g
    GArgs ghx0{p_zbuf, ZC_, w_init, ZC_, b_init, p_h0, H_, B_, H_, ZC_};
    GArgs gzi {p_zbuf, ZC_, w_ih_g + 130, 410, b_ih_g, p_zi, H3_, B_, H3_, ZC_};
    launch_gemm2(ghx0, gzi);

    // 8b. hx0 -> split-bf16
    convert_w_kernel<<<256, 256>>>(p_h0, sym_addr_bf(g_h0hi), sym_addr_bf(g_h0lo), BH_);

    // 9. persistent 2-layer decoder recurrence
    decoder_kernel<<<NB, 256, SMEM_R>>>(b_hh_g, b_ih_g2, b_hh_g2);

    // 10. batched output projection (tensor cores, h1 already split-bf16)
    launch_bf_gemm({sym_addr_bf(g_h1a_hi), sym_addr_bf(g_h1a_lo),
                    sym_addr_bf(g_wout_hi), sym_addr_bf(g_wout_lo),
                    b_out, p_logit, H_, H_, R_, R_, H_ / KCH});

    // 11. log_softmax
    logsoftmax_kernel<<<(int)((BT_ * 32 + 255) / 256), 256>>>(p_logit, out);
}